// round 13
// baseline (speedup 1.0000x reference)
#include <cuda_runtime.h>
#include <cmath>
#include <cstdint>

// Problem constants
#define B_   1024
#define ZD_  256
#define HD_  1024
#define L_   32
#define NW_  64
#define XD_  1024
#define H3   3072   // 3*HD

// ---------------- scratch (device globals: no runtime allocation) ----------
__device__ float g_GXALL[(size_t)L_ * B_ * H3];    // gx for all steps
__device__ float g_ZT[(size_t)L_ * B_ * HD_];      // z_theta per step (tf32)
__device__ float g_A1[(size_t)L_ * B_ * HD_];      // MLP hidden per step (tf32)
__device__ float g_WIH[(size_t)L_ * H3 * ZD_];     // repacked Wih[:, :256] (tf32)
__device__ float g_TW[(size_t)L_ * H3];            // Wih[:, 256] t-column (fp32)
__device__ float g_WHHS[(size_t)L_ * 16 * 32 * 192 * 32]; // Whh: per-(l,nb,ks) 24KB slabs, swizzled tf32
__device__ float g_W1[(size_t)L_ * HD_ * HD_];     // pW1 (tf32)
__device__ float g_W2[(size_t)L_ * NW_ * HD_];     // pW2 (tf32)
__device__ float g_WREC[(size_t)XD_ * HD_];        // recW (tf32)
__device__ float g_Z[(size_t)B_ * ZD_];            // z (tf32)

// ---------------- helpers ---------------------------------------------------
__device__ __forceinline__ float sigf(float x) { return 1.0f / (1.0f + expf(-x)); }

__device__ __forceinline__ float to_tf32(float x) {
    float r;
    asm("cvt.rna.tf32.f32 %0, %1;" : "=f"(r) : "f"(x));
    return r;
}

__device__ __forceinline__ void ldsm4(uint32_t* r, const void* p) {
    uint32_t a = (uint32_t)__cvta_generic_to_shared(p);
    asm volatile("ldmatrix.sync.aligned.m8n8.x4.shared.b16 {%0,%1,%2,%3}, [%4];"
                 : "=r"(r[0]), "=r"(r[1]), "=r"(r[2]), "=r"(r[3]) : "r"(a));
}

__device__ __forceinline__ void mma8(float* c, const uint32_t* a, uint32_t b0, uint32_t b1) {
    asm volatile("mma.sync.aligned.m16n8k8.row.col.f32.tf32.tf32.f32 "
                 "{%0,%1,%2,%3}, {%4,%5,%6,%7}, {%8,%9}, {%0,%1,%2,%3};"
                 : "+f"(c[0]), "+f"(c[1]), "+f"(c[2]), "+f"(c[3])
                 : "r"(a[0]), "r"(a[1]), "r"(a[2]), "r"(a[3]), "r"(b0), "r"(b1));
}

__device__ __forceinline__ void cpa16(void* dst, const void* src) {
    uint32_t d = (uint32_t)__cvta_generic_to_shared(dst);
    asm volatile("cp.async.cg.shared.global [%0], [%1], 16;" :: "r"(d), "l"(src));
}

__device__ __forceinline__ void mbar_init(uint32_t mbar, uint32_t count) {
    asm volatile("mbarrier.init.shared.b64 [%0], %1;" :: "r"(mbar), "r"(count) : "memory");
}
__device__ __forceinline__ void mbar_inval(uint32_t mbar) {
    asm volatile("mbarrier.inval.shared.b64 [%0];" :: "r"(mbar) : "memory");
}
__device__ __forceinline__ void mbar_expect_tx(uint32_t mbar, uint32_t bytes) {
    asm volatile("mbarrier.arrive.expect_tx.shared.b64 _, [%0], %1;"
                 :: "r"(mbar), "r"(bytes) : "memory");
}
__device__ __forceinline__ void mbar_wait(uint32_t mbar, uint32_t parity) {
    asm volatile(
        "{\n\t.reg .pred P;\n\t"
        "W_%=:\n\t"
        "mbarrier.try_wait.parity.acquire.cta.shared::cta.b64 P, [%0], %1, 0x989680;\n\t"
        "@!P bra W_%=;\n\t}"
        :: "r"(mbar), "r"(parity) : "memory");
}
__device__ __forceinline__ void mbar_arrive_cluster(uint32_t local_mbar, uint32_t rank) {
    asm volatile(
        "{\n\t.reg .b32 ra;\n\t"
        "mapa.shared::cluster.u32 ra, %0, %1;\n\t"
        "mbarrier.arrive.shared::cluster.b64 _, [ra];\n\t}"
        :: "r"(local_mbar), "r"(rank) : "memory");
}
__device__ __forceinline__ void bulk_mc(uint32_t dst, const void* src, uint32_t bytes,
                                        uint32_t mbar, uint16_t mask) {
    asm volatile(
        "cp.async.bulk.shared::cluster.global.mbarrier::complete_tx::bytes.multicast::cluster "
        "[%0], [%1], %2, [%3], %4;"
        :: "r"(dst), "l"(src), "r"(bytes), "r"(mbar), "h"(mask) : "memory");
}

// ---------------- prep kernels ----------------------------------------------
__global__ void cvt4(const float4* __restrict__ in, float4* __restrict__ out, int n4) {
    int i = blockIdx.x * blockDim.x + threadIdx.x;
    if (i >= n4) return;
    float4 v = in[i];
    v.x = to_tf32(v.x); v.y = to_tf32(v.y); v.z = to_tf32(v.z); v.w = to_tf32(v.w);
    out[i] = v;
}

__global__ void repack_wih(const float* __restrict__ Wih, float* __restrict__ out,
                           float* __restrict__ tw) {
    int q = blockIdx.x * blockDim.x + threadIdx.x;   // over L*H3*64 float4s
    if (q >= L_ * H3 * 64) return;
    const int j = q >> 6;            // row in [0, L*H3)
    const int k = (q & 63) * 4;
    const float* s = Wih + (size_t)j * (ZD_ + 1) + k;
    float4 v;
    v.x = to_tf32(s[0]); v.y = to_tf32(s[1]); v.z = to_tf32(s[2]); v.w = to_tf32(s[3]);
    *reinterpret_cast<float4*>(&out[(size_t)j * ZD_ + k]) = v;
    if ((q & 63) == 0) tw[j] = Wih[(size_t)j * (ZD_ + 1) + ZD_];
}

// Repack Whh into per-(l, nb, ks) contiguous 24KB slabs: [192 rows][8 chunks of 16B],
// with ldmatrix XOR-swizzle (chunk ^= row&7) pre-applied, values rna-rounded to tf32.
__global__ void repack_whh(const float* __restrict__ Whh, float* __restrict__ out) {
    size_t q = (size_t)blockIdx.x * blockDim.x + threadIdx.x;  // 16B chunk id
    if (q >= (size_t)L_ * 16 * 32 * 192 * 8) return;
    const int c_sw = (int)(q & 7);
    const int r    = (int)((q >> 3) % 192);
    const int ks   = (int)((q >> 3) / 192 % 32);
    const int nb   = (int)((q >> 3) / (192 * 32) % 16);
    const int l    = (int)((q >> 3) / (192 * 32 * 16));
    const int g = r >> 6, rr = r & 63;
    const size_t R = (size_t)l * H3 + g * HD_ + nb * 64 + rr;
    const int k = ks * 32 + ((c_sw ^ (r & 7)) << 2);
    const float* s = &Whh[R * HD_ + k];
    float4 v;
    v.x = to_tf32(s[0]); v.y = to_tf32(s[1]); v.z = to_tf32(s[2]); v.w = to_tf32(s[3]);
    reinterpret_cast<float4*>(out)[q] = v;
}

// ============================================================================
// Fused GRU step with cluster-8 multicast weights.
// Grid (16, 8), cluster (1,8,1): the 8 CTAs sharing a 64-col weight block form
// a cluster; each 24KB weight k-slab is fetched once (8 x 3KB cooperative
// slices, multicast to all). A (h rows) via per-CTA cp.async. 4-stage pipeline.
// ============================================================================
#define GMC_STAGES 4
#define GMC_ABYTES (128 * 36 * 4)                        // 18432
#define GMC_BBYTES (192 * 128)                           // 24576
#define GMC_ABASE  128
#define GMC_BBASE  (GMC_ABASE + GMC_STAGES * GMC_ABYTES) // 73856
#define GMC_SMEM   (GMC_BBASE + GMC_STAGES * GMC_BBYTES) // 172160

__global__ __launch_bounds__(256) __cluster_dims__(1, 8, 1)
void gemm_gru_mc(const float* __restrict__ h,       // [B, HD] prev z_theta (tf32)
                 const float* __restrict__ Wslab,   // slabs for this l: [16][32][192][32]
                 const float* __restrict__ bhh_l,   // [3*HD]
                 const float* __restrict__ gx_l,    // [B, 3*HD]
                 const float* __restrict__ eps_l,   // [B, HD]
                 float* __restrict__ zt_out)        // [B, HD]
{
    extern __shared__ char smem_raw[];
    const uint32_t smem_u32 = (uint32_t)__cvta_generic_to_shared(smem_raw);
    const uint32_t mb_full  = smem_u32;        // 4 x 8B
    const uint32_t mb_empty = smem_u32 + 32;   // 4 x 8B

    const int n0 = blockIdx.x * 64;
    const int m0 = blockIdx.y * 128;
    const int tid = threadIdx.x;
    const int lane = tid & 31;
    const int warp = tid >> 5;
    const int wm = warp >> 2;
    const int wn = warp & 3;
    uint32_t rank;
    asm("mov.u32 %0, %%cluster_ctarank;" : "=r"(rank));
    const int nIter = HD_ / 32;  // 32

    if (tid == 0) {
#pragma unroll
        for (int s = 0; s < GMC_STAGES; s++) {
            mbar_init(mb_full + s * 8, 1);
            mbar_init(mb_empty + s * 8, 8);
        }
    }
    __syncthreads();
    asm volatile("barrier.cluster.arrive.aligned;" ::: "memory");
    asm volatile("barrier.cluster.wait.aligned;" ::: "memory");

    float acc[3][8][4];
#pragma unroll
    for (int g = 0; g < 3; g++)
#pragma unroll
        for (int i = 0; i < 8; i++)
            acc[g][i][0] = acc[g][i][1] = acc[g][i][2] = acc[g][i][3] = 0.0f;

    auto issueA = [&](int it) {
        float* As = (float*)(smem_raw + GMC_ABASE + (it & 3) * GMC_ABYTES);
        const int k0 = it * 32;
#pragma unroll
        for (int i = 0; i < 4; i++) {
            const int idx = tid + i * 256;
            const int r = idx >> 3, c = idx & 7;
            cpa16(&As[r * 36 + c * 4], &h[(size_t)(m0 + r) * HD_ + k0 + c * 4]);
        }
        asm volatile("cp.async.commit_group;");
    };
    auto issueB = [&](int it) {   // tid 0 only
        const int s = it & 3;
        mbar_expect_tx(mb_full + s * 8, GMC_BBYTES);
        const char* src = (const char*)(Wslab + ((size_t)blockIdx.x * 32 + it) * 6144)
                          + rank * 3072;
        bulk_mc(smem_u32 + GMC_BBASE + s * GMC_BBYTES + rank * 3072, src, 3072,
                mb_full + s * 8, (uint16_t)0xFF);
    };

    // prologue: fill 4 stages
    if (tid == 0) {
#pragma unroll
        for (int p = 0; p < GMC_STAGES; p++) issueB(p);
    }
#pragma unroll
    for (int p = 0; p < GMC_STAGES; p++) issueA(p);

    const int arow = wm * 64 + (lane & 7) + ((lane >> 3) & 1) * 8;
    const int akc  = ((lane >> 4) & 1) * 4;
    const int brow = wn * 16 + (lane & 7) + ((lane >> 4) & 1) * 8;
    const int bkc  = ((lane >> 3) & 1) * 4;

    for (int it = 0; it < nIter; it++) {
        const int s = it & 3;
        const uint32_t par = (uint32_t)((it >> 2) & 1);
        asm volatile("cp.async.wait_group %0;" :: "n"(GMC_STAGES - 1));
        mbar_wait(mb_full + s * 8, par);
        __syncthreads();   // everyone's A chunks visible; all passed waits

        const float* As = (const float*)(smem_raw + GMC_ABASE + s * GMC_ABYTES);
        const char*  Bs = smem_raw + GMC_BBASE + s * GMC_BBYTES;
#pragma unroll
        for (int ks = 0; ks < 4; ks++) {
            uint32_t af[4][4], bf[3][4];
#pragma unroll
            for (int mt = 0; mt < 4; mt++)
                ldsm4(af[mt], &As[(arow + mt * 16) * 36 + ks * 8 + akc]);
            const int cI = ks * 2 + (bkc >> 2);
#pragma unroll
            for (int g = 0; g < 3; g++) {
                const int r = g * 64 + brow;
                ldsm4(bf[g], Bs + r * 128 + ((cI ^ (r & 7)) << 4));
            }
#pragma unroll
            for (int g = 0; g < 3; g++)
#pragma unroll
                for (int mt = 0; mt < 4; mt++)
#pragma unroll
                    for (int nt = 0; nt < 2; nt++)
                        mma8(acc[g][mt * 2 + nt], af[mt], bf[g][nt * 2], bf[g][nt * 2 + 1]);
        }
        __syncthreads();   // all done reading stage s

        if (tid == 0) {
#pragma unroll
            for (int k = 0; k < 8; k++) mbar_arrive_cluster(mb_empty + s * 8, k);
        }
        if (it + GMC_STAGES < nIter) {
            if (tid == 0) {
                mbar_wait(mb_empty + s * 8, par);  // all 8 CTAs consumed this round
                issueB(it + GMC_STAGES);
            }
            issueA(it + GMC_STAGES);
        }
    }

    // ---- fused gate epilogue ----
    const float STD = 1.0025031276057952f; // exp(0.5*0.005)
#pragma unroll
    for (int nt = 0; nt < 2; nt++) {
        const int c = n0 + wn * 16 + nt * 8 + 2 * (lane & 3);
        const float2 br = *reinterpret_cast<const float2*>(&bhh_l[c]);
        const float2 bu = *reinterpret_cast<const float2*>(&bhh_l[HD_ + c]);
        const float2 bn = *reinterpret_cast<const float2*>(&bhh_l[2 * HD_ + c]);
#pragma unroll
        for (int mt = 0; mt < 4; mt++) {
#pragma unroll
            for (int half = 0; half < 2; half++) {
                const int r = m0 + wm * 64 + mt * 16 + (lane >> 2) + half * 8;
                const size_t o3 = (size_t)r * H3 + c;
                const size_t o1 = (size_t)r * HD_ + c;
                const float2 xr = *reinterpret_cast<const float2*>(&gx_l[o3]);
                const float2 xu = *reinterpret_cast<const float2*>(&gx_l[o3 + HD_]);
                const float2 xn = *reinterpret_cast<const float2*>(&gx_l[o3 + 2 * HD_]);
                const float2 hp = *reinterpret_cast<const float2*>(&h[o1]);
                const float2 ep = *reinterpret_cast<const float2*>(&eps_l[o1]);
                const float hr0 = acc[0][mt * 2 + nt][half * 2 + 0] + br.x;
                const float hr1 = acc[0][mt * 2 + nt][half * 2 + 1] + br.y;
                const float hu0 = acc[1][mt * 2 + nt][half * 2 + 0] + bu.x;
                const float hu1 = acc[1][mt * 2 + nt][half * 2 + 1] + bu.y;
                const float hn0 = acc[2][mt * 2 + nt][half * 2 + 0] + bn.x;
                const float hn1 = acc[2][mt * 2 + nt][half * 2 + 1] + bn.y;
                const float r0 = sigf(xr.x + hr0), r1 = sigf(xr.y + hr1);
                const float u0 = sigf(xu.x + hu0), u1 = sigf(xu.y + hu1);
                const float n0v = tanhf(xn.x + r0 * hn0), n1v = tanhf(xn.y + r1 * hn1);
                float2 o;
                o.x = to_tf32((1.0f - u0) * n0v + u0 * hp.x + STD * ep.x);
                o.y = to_tf32((1.0f - u1) * n1v + u1 * hp.y + STD * ep.y);
                *reinterpret_cast<float2*>(&zt_out[o1]) = o;
            }
        }
    }

    __syncthreads();
    if (tid == 0) {
#pragma unroll
        for (int s = 0; s < GMC_STAGES; s++) {
            mbar_inval(mb_full + s * 8);
            mbar_inval(mb_empty + s * 8);
        }
    }
    asm volatile("barrier.cluster.arrive.aligned;" ::: "memory");
    asm volatile("barrier.cluster.wait.aligned;" ::: "memory");
}

// ============================================================================
// Generic TF32 NT GEMM, cp.async 3-stage, BK=16, 128x128 tile (unchanged, passing).
// ============================================================================
#define CA_PAD  20
#define CA_STG  ((128 + 128) * CA_PAD)   // 5120 floats per stage
#define CA_SMEM (3 * CA_STG * 4)         // 61440 bytes

struct GP {
    const float* A;    size_t sA; int lda;
    const float* Bm;   size_t sB; int ldb;
    float*       C;    size_t sC; int ldc;
    const float* bias; size_t sBias;
    const float* tw;
    const float* tmat;
    int M, N, K, mode;
};

__global__ __launch_bounds__(256)
void gemm_ca(GP p) {
    extern __shared__ float smem[];
    const int l = blockIdx.z;
    const float* A    = p.A    + (size_t)l * p.sA;
    const float* Bm   = p.Bm   + (size_t)l * p.sB;
    const float* bias = p.bias + (size_t)l * p.sBias;

    const int m0 = blockIdx.y * 128;
    const int n0 = blockIdx.x * 128;
    const int tid = threadIdx.x;
    const int lane = tid & 31;
    const int warp = tid >> 5;
    const int wm = warp >> 2;
    const int wn = warp & 3;
    const int nIter = p.K / 16;

    float acc[16][4];
#pragma unroll
    for (int i = 0; i < 16; i++)
        acc[i][0] = acc[i][1] = acc[i][2] = acc[i][3] = 0.0f;

    auto issue = [&](int it) {
        if (it < nIter) {
            float* As = smem + (it % 3) * CA_STG;
            float* Bs = As + 128 * CA_PAD;
            const int k0 = it * 16;
#pragma unroll
            for (int i = 0; i < 2; i++) {
                const int idx = tid + i * 256;
                const int r = idx >> 2, c = idx & 3;
                cpa16(&As[r * CA_PAD + c * 4], &A[(size_t)(m0 + r) * p.lda + k0 + c * 4]);
            }
#pragma unroll
            for (int i = 0; i < 2; i++) {
                const int idx = tid + i * 256;
                const int r = idx >> 2, c = idx & 3;
                const int n = min(n0 + r, p.N - 1);
                cpa16(&Bs[r * CA_PAD + c * 4], &Bm[(size_t)n * p.ldb + k0 + c * 4]);
            }
        }
        asm volatile("cp.async.commit_group;");
    };

    issue(0);
    issue(1);

    const int arow = wm * 64 + (lane & 7) + ((lane >> 3) & 1) * 8;
    const int akc0 = ((lane >> 4) & 1) * 4;
    const int brow = wn * 32 + (lane & 7) + ((lane >> 4) & 1) * 8;
    const int bkc0 = ((lane >> 3) & 1) * 4;

    for (int it = 0; it < nIter; it++) {
        asm volatile("cp.async.wait_group 1;");
        __syncthreads();
        issue(it + 2);
        float* As = smem + (it % 3) * CA_STG;
        float* Bs = As + 128 * CA_PAD;
#pragma unroll
        for (int ks = 0; ks < 2; ks++) {
            uint32_t af[4][4], bf[2][4];
#pragma unroll
            for (int mt = 0; mt < 4; mt++)
                ldsm4(af[mt], &As[(arow + mt * 16) * CA_PAD + ks * 8 + akc0]);
#pragma unroll
            for (int bt = 0; bt < 2; bt++)
                ldsm4(bf[bt], &Bs[(brow + bt * 16) * CA_PAD + ks * 8 + bkc0]);
#pragma unroll
            for (int mt = 0; mt < 4; mt++)
#pragma unroll
                for (int nt = 0; nt < 4; nt++)
                    mma8(acc[mt * 4 + nt], af[mt],
                         bf[nt >> 1][(nt & 1) * 2], bf[nt >> 1][(nt & 1) * 2 + 1]);
        }
    }

    float* C = p.C + (size_t)l * p.sC;
#pragma unroll
    for (int mt = 0; mt < 4; mt++) {
        const int r = m0 + wm * 64 + mt * 16 + (lane >> 2);
#pragma unroll
        for (int nt = 0; nt < 4; nt++) {
            const int c = n0 + wn * 32 + nt * 8 + 2 * (lane & 3);
            float* a = acc[mt * 4 + nt];
            if (p.mode == 4 && c >= p.N) continue;

            float b0 = bias[c], b1 = bias[c + 1];
            float v00 = a[0] + b0, v01 = a[1] + b1;
            float v10 = a[2] + b0, v11 = a[3] + b1;

            if (p.mode == 1) {
                const float w0 = p.tw[(size_t)l * H3 + c];
                const float w1 = p.tw[(size_t)l * H3 + c + 1];
                const float t0 = p.tmat[(size_t)r * L_ + l];
                const float t1 = p.tmat[(size_t)(r + 8) * L_ + l];
                v00 += t0 * w0; v01 += t0 * w1;
                v10 += t1 * w0; v11 += t1 * w1;
            } else if (p.mode == 2) {
                v00 = to_tf32(fmaxf(v00, 0.f)); v01 = to_tf32(fmaxf(v01, 0.f));
                v10 = to_tf32(fmaxf(v10, 0.f)); v11 = to_tf32(fmaxf(v11, 0.f));
            } else if (p.mode == 3) {
                v00 = sigf(v00); v01 = sigf(v01);
                v10 = sigf(v10); v11 = sigf(v11);
            } else if (p.mode == 4) {
                v00 = sigf(v00); v01 = sigf(v01);
                v10 = sigf(v10); v11 = sigf(v11);
                p.C[((size_t)c       * B_ + r)     * L_ + l] = v00;
                p.C[((size_t)(c + 1) * B_ + r)     * L_ + l] = v01;
                p.C[((size_t)c       * B_ + r + 8) * L_ + l] = v10;
                p.C[((size_t)(c + 1) * B_ + r + 8) * L_ + l] = v11;
                continue;
            }
            *reinterpret_cast<float2*>(&C[(size_t)r * p.ldc + c]) = make_float2(v00, v01);
            *reinterpret_cast<float2*>(&C[(size_t)(r + 8) * p.ldc + c]) = make_float2(v10, v11);
        }
    }
}

// ---------------- first-step gate (h0 = 0, gh = bhh) -------------------------
__device__ __forceinline__ float gru_one0(float xr, float xu, float xn,
                                          float hr, float hu, float hn, float ep) {
    const float STD = 1.0025031276057952f;
    float r = sigf(xr + hr);
    float u = sigf(xu + hu);
    float n = tanhf(xn + r * hn);
    return (1.0f - u) * n + STD * ep;
}

__global__ void gru_gate0(const float* __restrict__ gx, const float* __restrict__ bhh,
                          const float* __restrict__ eps, float* __restrict__ hnew) {
    const int i4 = blockIdx.x * blockDim.x + threadIdx.x;
    if (i4 >= B_ * HD_ / 4) return;
    const int idx = i4 << 2;
    const int b = idx >> 10;
    const int j = idx & (HD_ - 1);
    const size_t o3 = (size_t)b * H3 + j;
    const size_t o1 = (size_t)b * HD_ + j;

    float4 xr = *reinterpret_cast<const float4*>(&gx[o3]);
    float4 xu = *reinterpret_cast<const float4*>(&gx[o3 + HD_]);
    float4 xn = *reinterpret_cast<const float4*>(&gx[o3 + 2 * HD_]);
    float4 hr = *reinterpret_cast<const float4*>(&bhh[j]);
    float4 hu = *reinterpret_cast<const float4*>(&bhh[j + HD_]);
    float4 hn = *reinterpret_cast<const float4*>(&bhh[j + 2 * HD_]);
    float4 ep = *reinterpret_cast<const float4*>(&eps[o1]);

    float4 o;
    o.x = to_tf32(gru_one0(xr.x, xu.x, xn.x, hr.x, hu.x, hn.x, ep.x));
    o.y = to_tf32(gru_one0(xr.y, xu.y, xn.y, hr.y, hu.y, hn.y, ep.y));
    o.z = to_tf32(gru_one0(xr.z, xu.z, xn.z, hr.z, hu.z, hn.z, ep.z));
    o.w = to_tf32(gru_one0(xr.w, xu.w, xn.w, hr.w, hu.w, hn.w, ep.w));
    *reinterpret_cast<float4*>(&hnew[o1]) = o;
}

// ---------------- launch ----------------------------------------------------
extern "C" void kernel_launch(void* const* d_in, const int* in_sizes, int n_in,
                              void* d_out, int out_size) {
    const float* z    = (const float*)d_in[0];
    const float* t    = (const float*)d_in[1];
    const float* eps  = (const float*)d_in[2];
    const float* Wih  = (const float*)d_in[3];
    const float* Whh  = (const float*)d_in[4];
    const float* bih  = (const float*)d_in[5];
    const float* bhh  = (const float*)d_in[6];
    const float* pW1  = (const float*)d_in[7];
    const float* pb1  = (const float*)d_in[8];
    const float* pW2  = (const float*)d_in[9];
    const float* pb2  = (const float*)d_in[10];
    const float* recW = (const float*)d_in[11];
    const float* recb = (const float*)d_in[12];

    float* out       = (float*)d_out;
    float* out_recon = out;                          // [B, XD]
    float* out_pred  = out + (size_t)B_ * XD_;       // [NW, B, L]

    float *GX, *ZT, *A1, *WIH, *TW, *WHHS, *W1, *W2, *WREC, *Zc;
    cudaGetSymbolAddress((void**)&GX,   g_GXALL);
    cudaGetSymbolAddress((void**)&ZT,   g_ZT);
    cudaGetSymbolAddress((void**)&A1,   g_A1);
    cudaGetSymbolAddress((void**)&WIH,  g_WIH);
    cudaGetSymbolAddress((void**)&TW,   g_TW);
    cudaGetSymbolAddress((void**)&WHHS, g_WHHS);
    cudaGetSymbolAddress((void**)&W1,   g_W1);
    cudaGetSymbolAddress((void**)&W2,   g_W2);
    cudaGetSymbolAddress((void**)&WREC, g_WREC);
    cudaGetSymbolAddress((void**)&Zc,   g_Z);

    cudaFuncSetAttribute(gemm_gru_mc, cudaFuncAttributeMaxDynamicSharedMemorySize, GMC_SMEM);
    cudaFuncSetAttribute(gemm_ca,     cudaFuncAttributeMaxDynamicSharedMemorySize, CA_SMEM);

    // 0) prep: tf32-round + repack all GEMM operands
    {
        const int T = 256;
        int n;
        n = L_ * H3 * 64;                 repack_wih<<<(n + T - 1) / T, T>>>(Wih, WIH, TW);
        n = (B_ * ZD_) / 4;               cvt4<<<(n + T - 1) / T, T>>>((const float4*)z, (float4*)Zc, n);
        {
            size_t nq = (size_t)L_ * 16 * 32 * 192 * 8;
            repack_whh<<<(unsigned)((nq + T - 1) / T), T>>>(Whh, WHHS);
        }
        n = (int)(((size_t)L_ * HD_ * HD_) / 4); cvt4<<<(n + T - 1) / T, T>>>((const float4*)pW1, (float4*)W1, n);
        n = (L_ * NW_ * HD_) / 4;         cvt4<<<(n + T - 1) / T, T>>>((const float4*)pW2, (float4*)W2, n);
        n = (XD_ * HD_) / 4;              cvt4<<<(n + T - 1) / T, T>>>((const float4*)recW, (float4*)WREC, n);
    }

    // 1) gx_all[l] = z @ WihZ_l^T + t[:,l] ⊗ tw_l + bih_l   (L-parallel)
    {
        GP p{};
        p.A = Zc;  p.sA = 0;                       p.lda = ZD_;
        p.Bm = WIH; p.sB = (size_t)H3 * ZD_;       p.ldb = ZD_;
        p.C = GX;  p.sC = (size_t)B_ * H3;         p.ldc = H3;
        p.bias = bih; p.sBias = H3;
        p.tw = TW; p.tmat = t;
        p.M = B_; p.N = H3; p.K = ZD_; p.mode = 1;
        gemm_ca<<<dim3(H3 / 128, B_ / 128, L_), 256, CA_SMEM>>>(p);
    }

    // 2) sequential GRU scan: fused multicast GEMM + gates per step
    gru_gate0<<<(B_ * HD_ / 4 + 255) / 256, 256>>>(GX, bhh, eps, ZT);
    for (int l = 1; l < L_; l++) {
        gemm_gru_mc<<<dim3(16, 8), 256, GMC_SMEM>>>(
            ZT + (size_t)(l - 1) * B_ * HD_,
            WHHS + (size_t)l * 16 * 32 * 192 * 32,
            bhh + (size_t)l * H3,
            GX + (size_t)l * B_ * H3,
            eps + (size_t)l * B_ * HD_,
            ZT + (size_t)l * B_ * HD_);
    }

    // 3) MLP hidden: A1[l] = tf32(relu(z_theta[l] @ pW1_l^T + pb1_l))   (L-parallel)
    {
        GP p{};
        p.A = ZT;  p.sA = (size_t)B_ * HD_;   p.lda = HD_;
        p.Bm = W1; p.sB = (size_t)HD_ * HD_;  p.ldb = HD_;
        p.C = A1;  p.sC = (size_t)B_ * HD_;   p.ldc = HD_;
        p.bias = pb1; p.sBias = HD_;
        p.M = B_; p.N = HD_; p.K = HD_; p.mode = 2;
        gemm_ca<<<dim3(HD_ / 128, B_ / 128, L_), 256, CA_SMEM>>>(p);
    }

    // 4) preds: sigmoid(A1[l] @ pW2_l^T + pb2_l), stored [NW, B, L]   (L-parallel)
    {
        GP p{};
        p.A = A1;  p.sA = (size_t)B_ * HD_;   p.lda = HD_;
        p.Bm = W2; p.sB = (size_t)NW_ * HD_;  p.ldb = HD_;
        p.C = out_pred; p.sC = 0; p.ldc = 0;
        p.bias = pb2; p.sBias = NW_;
        p.M = B_; p.N = NW_; p.K = HD_; p.mode = 4;
        gemm_ca<<<dim3(1, B_ / 128, L_), 256, CA_SMEM>>>(p);
    }

    // 5) recon = sigmoid(hT @ recW^T + recb)
    {
        GP p{};
        p.A = ZT + (size_t)(L_ - 1) * B_ * HD_; p.sA = 0; p.lda = HD_;
        p.Bm = WREC; p.sB = 0; p.ldb = HD_;
        p.C = out_recon; p.sC = 0; p.ldc = XD_;
        p.bias = recb; p.sBias = 0;
        p.M = B_; p.N = XD_; p.K = HD_; p.mode = 3;
        gemm_ca<<<dim3(XD_ / 128, B_ / 128, 1), 256, CA_SMEM>>>(p);
    }
}